// round 16
// baseline (speedup 1.0000x reference)
#include <cuda_runtime.h>
#include <math.h>

#define NL 8
#define NB 16
#define NT 80
#define ND 512
#define NH 8
#define HDIM 64
#define NV 8000
#define NPR 64
#define NNEW 16
#define NFF 2048
#define NROWS (NB*NPR)
#define NBLK 128
#define NGRP 4
#define GBLK 32
#define RPG 4

// ------------------------- device state -------------------------
__device__ float g_x[NROWS*ND];
__device__ float g_h[NROWS*ND];
__device__ float g_qkv[NROWS*3*ND];
__device__ float g_attn[NROWS*ND];
__device__ float g_ff[NROWS*NFF];
__device__ float g_K[NL*NB*NH*NT*HDIM];
__device__ float g_V[NL*NB*NH*NT*HDIM];
__device__ float g_xA[NB*ND];
__device__ float g_xB[NB*ND];
__device__ float g_h16[NB*ND];          // LN1 output
__device__ float g_h2[NB*ND];           // LN2 output
__device__ float g_lnf16[NB*ND];
__device__ float g_pQ[16*NB*3*ND];      // qkv partials: 16 kchunks of 32
__device__ float g_pAO[NH*NB*ND];       // per-head ao partials
__device__ float g_pFC[16*NB*NFF];      // fc partials: 16 kchunks of 32
__device__ float g_pPR[32*NB*ND];       // pr partials: 32 kchunks of 64
__device__ float g_pLM[4*NB*NV];        // lm partials: 4 kchunks of 128
__device__ int   g_ids[NB*NT];
__device__ int   g_lens[NB];
__device__ int   g_fin[NB];
__device__ float g_csum[NB];
__device__ float g_ccnt[NB];
__device__ unsigned int g_garr[NGRP*32];
__device__ unsigned int g_grel[NGRP*32];

// ------------------------- helpers -------------------------
__device__ __forceinline__ float warpReduceSum(float v){
  #pragma unroll
  for(int o=16;o>0;o>>=1) v += __shfl_xor_sync(0xffffffffu, v, o);
  return v;
}
__device__ __forceinline__ float warpReduceMax(float v){
  #pragma unroll
  for(int o=16;o>0;o>>=1) v = fmaxf(v, __shfl_xor_sync(0xffffffffu, v, o));
  return v;
}
__device__ __forceinline__ float blockReduceSum(float v, float* sh){
  int tid=threadIdx.x;
  v = warpReduceSum(v);
  if((tid&31)==0) sh[tid>>5]=v;
  __syncthreads();
  int nw=(blockDim.x+31)>>5;
  float r = (tid < nw)? sh[tid] : 0.f;
  if (tid<32) r = warpReduceSum(r);
  if (tid==0) sh[0]=r;
  __syncthreads();
  r = sh[0];
  __syncthreads();
  return r;
}
__device__ __forceinline__ float blockReduceMax(float v, float* sh){
  int tid=threadIdx.x;
  v = warpReduceMax(v);
  if((tid&31)==0) sh[tid>>5]=v;
  __syncthreads();
  int nw=(blockDim.x+31)>>5;
  float r = (tid < nw)? sh[tid] : -3.4e38f;
  if (tid<32) r = warpReduceMax(r);
  if (tid==0) sh[0]=r;
  __syncthreads();
  r = sh[0];
  __syncthreads();
  return r;
}
__device__ __forceinline__ float geluf(float x){
  float x3=x*x*x;
  return 0.5f*x*(1.f+tanhf(0.7978845608028654f*(x+0.044715f*x3)));
}
__device__ __forceinline__ void gsyncg(int g, unsigned int &gen){
  __syncthreads();
  if(threadIdx.x==0){
    gen += 1u;
    __threadfence();
    unsigned int old=atomicAdd(&g_garr[g*32],1u);
    if(old == gen*GBLK - 1u){
      *((volatile unsigned int*)&g_grel[g*32]) = gen;
      __threadfence();
    }else{
      while(*((volatile unsigned int*)&g_grel[g*32]) < gen) {}
    }
    __threadfence();
  }
  __syncthreads();
}

// ------------------------- setup -------------------------
__global__ void k_init(const int* __restrict__ ids, const int* __restrict__ mask){
  int tid=threadIdx.x;
  if(tid<NGRP){ g_garr[tid*32]=0u; g_grel[tid*32]=0u; }
  for(int i=tid;i<NB*NT;i+=blockDim.x) g_ids[i]=ids[i];
  if(tid<NB){
    int s=0;
    for(int t=0;t<NT;t++) s += (mask[tid*NT+t]>0)?1:0;
    g_lens[tid]=s; g_fin[tid]=0; g_csum[tid]=0.f; g_ccnt[tid]=0.f;
  }
}

__global__ void k_embed_pre(const float* __restrict__ wte, const float* __restrict__ wpe){
  int p=blockIdx.x, b=blockIdx.y;
  int id=g_ids[b*NT+p];
  int row=b*NPR+p;
  for(int d=threadIdx.x; d<ND; d+=blockDim.x)
    g_x[(size_t)row*ND+d] = wte[(size_t)id*ND+d] + wpe[(size_t)p*ND+d];
}

__global__ void k_ln(const float* __restrict__ X, float* __restrict__ Y,
                     const float* __restrict__ w, const float* __restrict__ bb){
  __shared__ float sh[32];
  int r=blockIdx.x;
  const float* x=X+(size_t)r*ND;
  float s=0.f,s2=0.f;
  for(int i=threadIdx.x;i<ND;i+=blockDim.x){float v=x[i]; s+=v; s2+=v*v;}
  s  = blockReduceSum(s, sh);
  s2 = blockReduceSum(s2, sh);
  float mean=s/(float)ND;
  float var=s2/(float)ND-mean*mean;
  float rstd=1.f/sqrtf(var+1e-5f);
  for(int i=threadIdx.x;i<ND;i+=blockDim.x){
    float v=x[i];
    Y[(size_t)r*ND+i]=(v-mean)*rstd*w[i]+bb[i];
  }
}

// ------------------------- prefill kernels -------------------------
// 64x128 tile, 128 threads, 8x8 per-thread micro-tile, float4 smem loads.
// Same k-summation order as before (k0 tiles of 16, kk ascending) => bit-identical.
template<int EPI>
__global__ void k_gemm(const float* __restrict__ A, const float* __restrict__ W,
                       const float* __restrict__ bias, float* __restrict__ C,
                       const float* __restrict__ R, int M, int N, int K){
  __shared__ float As[16*68];    // [kk][row], padded stride 68
  __shared__ float Ws[16*128];   // [kk][col]
  int tid=threadIdx.x;
  int tx=tid&15, ty=tid>>4;      // tx: 16 col-groups of 8, ty: 8 row-groups of 8
  int row0=blockIdx.y*64, col0=blockIdx.x*128;
  float acc[8][8];
  #pragma unroll
  for(int i=0;i<8;i++)
    #pragma unroll
    for(int j=0;j<8;j++) acc[i][j]=0.f;

  for(int k0=0;k0<K;k0+=16){
    #pragma unroll
    for(int i=0;i<8;i++){
      int idx=tid+i*128;                 // 1024 A elems
      int r=idx>>4, kk=idx&15;
      As[kk*68+r]=A[(size_t)(row0+r)*K + k0+kk];
    }
    #pragma unroll
    for(int i=0;i<16;i++){
      int idx=tid+i*128;                 // 2048 W elems
      int kk=idx>>7, c=idx&127;
      Ws[kk*128+c]=W[(size_t)(k0+kk)*N + col0+c];
    }
    __syncthreads();
    #pragma unroll
    for(int kk=0;kk<16;kk++){
      float4 a0=*(const float4*)&As[kk*68+ty*8];
      float4 a1=*(const float4*)&As[kk*68+ty*8+4];
      float4 w0=*(const float4*)&Ws[kk*128+tx*8];
      float4 w1=*(const float4*)&Ws[kk*128+tx*8+4];
      float av[8]={a0.x,a0.y,a0.z,a0.w,a1.x,a1.y,a1.z,a1.w};
      float wv[8]={w0.x,w0.y,w0.z,w0.w,w1.x,w1.y,w1.z,w1.w};
      #pragma unroll
      for(int i=0;i<8;i++)
        #pragma unroll
        for(int j=0;j<8;j++)
          acc[i][j] += av[i]*wv[j];
    }
    __syncthreads();
  }
  #pragma unroll
  for(int i=0;i<8;i++){
    int row=row0+ty*8+i;
    #pragma unroll
    for(int j=0;j<8;j++){
      int col=col0+tx*8+j;
      float v=acc[i][j]+bias[col];
      if(EPI==1) v += R[(size_t)row*N+col];
      if(EPI==2) v = geluf(v);
      C[(size_t)row*N+col]=v;
    }
  }
}

__global__ void k_attn_pre(int layer){
  __shared__ float Ks[64*65];
  __shared__ float Vs[64*65];
  __shared__ float qsm[8*64];
  __shared__ float psm[8*64];
  int hh=blockIdx.x, b=blockIdx.y;
  int tid=threadIdx.x;
  size_t base=((((size_t)layer*NB+b)*NH+hh)*(size_t)NT)*HDIM;
  for(int idx=tid; idx<64*64; idx+=256){
    int k=idx>>6, d=idx&63;
    size_t src=(size_t)(b*NPR+k)*3*ND + hh*HDIM + d;
    float kv=g_qkv[src+ND];
    float vv=g_qkv[src+2*ND];
    Ks[k*65+d]=kv; Vs[k*65+d]=vv;
    g_K[base+(size_t)k*HDIM+d]=kv;
    g_V[base+(size_t)k*HDIM+d]=vv;
  }
  __syncthreads();
  int w=tid>>5, lane=tid&31;
  for(int qi=0;qi<8;qi++){
    int p=w*8+qi;
    int row=b*NPR+p;
    const float* qp=&g_qkv[(size_t)row*3*ND + hh*HDIM];
    qsm[w*64+lane]=qp[lane];
    qsm[w*64+lane+32]=qp[lane+32];
    __syncwarp();
    float s0=0.f,s1=0.f;
    #pragma unroll 8
    for(int d=0;d<64;d++){
      float qd=qsm[w*64+d];
      s0+=qd*Ks[lane*65+d];
      s1+=qd*Ks[(lane+32)*65+d];
    }
    s0 = s0*0.125f + ((lane   <=p)?0.f:-1e9f);
    s1 = s1*0.125f + ((lane+32<=p)?0.f:-1e9f);
    float m = warpReduceMax(fmaxf(s0,s1));
    float e0=expf(s0-m), e1=expf(s1-m);
    float sum=warpReduceSum(e0+e1);
    float inv=1.f/sum;
    psm[w*64+lane]=e0*inv;
    psm[w*64+lane+32]=e1*inv;
    __syncwarp();
    float o0=0.f,o1=0.f;
    #pragma unroll 8
    for(int k=0;k<64;k++){
      float pk=psm[w*64+k];
      o0+=pk*Vs[k*65+lane];
      o1+=pk*Vs[k*65+lane+32];
    }
    g_attn[(size_t)row*ND+hh*HDIM+lane]   =o0;
    g_attn[(size_t)row*ND+hh*HDIM+lane+32]=o1;
    __syncwarp();
  }
}

__global__ void k_gather_last(){
  int b=blockIdx.x;
  int p=min(max(g_lens[b]-1,0),NPR-1);
  for(int d=threadIdx.x; d<ND; d+=blockDim.x)
    g_xA[(size_t)b*ND+d]=g_x[(size_t)(b*NPR+p)*ND+d];
}

// ------------------------- group decode stages (R12, NGRP=4) -------------------------
#define FMA4(wv,xv) \
  a0.x+=xv.x*wv.x; a0.y+=xv.x*wv.y; a0.z+=xv.x*wv.z; a0.w+=xv.x*wv.w; \
  a1.x+=xv.y*wv.x; a1.y+=xv.y*wv.y; a1.z+=xv.y*wv.z; a1.w+=xv.y*wv.w; \
  a2.x+=xv.z*wv.x; a2.y+=xv.z*wv.y; a2.z+=xv.z*wv.z; a2.w+=xv.z*wv.w; \
  a3.x+=xv.w*wv.x; a3.y+=xv.w*wv.y; a3.z+=xv.w*wv.z; a3.w+=xv.w*wv.w;

// S1 qkv: cb=lid&1 (2 x 768 cols), ch=lid>>1 (16 x 32 k). batched prefetch.
__device__ __forceinline__ void st_qkv_g(int r0,int lid,const float* W,float* sm){
  float* xs=sm;  // [32][4]
  int tid=threadIdx.x;
  int cb=lid&1, ch=lid>>1;
  int k0=ch*32;
  if(tid<128){
    int r=tid&3, kk=tid>>2;
    xs[kk*4+r]=__ldcv(&g_h16[(r0+r)*ND + k0+kk]);
  }
  __syncthreads();
  if(tid<192){
    int col=cb*768+tid*4;
    float4 a0={0,0,0,0},a1={0,0,0,0},a2={0,0,0,0},a3={0,0,0,0};
    const float4* Wp=(const float4*)(W+(size_t)k0*(3*ND)+col);
    const int str=(3*ND)/4;
    #pragma unroll
    for(int t2=0;t2<2;t2++){
      float4 wb[16];
      #pragma unroll
      for(int u=0;u<16;u++) wb[u]=__ldg(Wp+u*str);
      Wp+=16*str;
      #pragma unroll
      for(int u=0;u<16;u++){
        float4 xv=*(const float4*)&xs[(t2*16+u)*4];
        FMA4(wb[u],xv)
      }
    }
    *(float4*)&g_pQ[((size_t)ch*NB+(r0+0))*(3*ND)+col]=a0;
    *(float4*)&g_pQ[((size_t)ch*NB+(r0+1))*(3*ND)+col]=a1;
    *(float4*)&g_pQ[((size_t)ch*NB+(r0+2))*(3*ND)+col]=a2;
    *(float4*)&g_pQ[((size_t)ch*NB+(r0+3))*(3*ND)+col]=a3;
  }
  __syncthreads();
}

// S2 attn: 32 tasks (4 rows x 8 heads)
__device__ __forceinline__ void st_attn_g(int r0,int lid,int layer,const float* qb,
                                          const float* aw,float* sm){
  float* qs=sm; float* os=sm+64; float* sc=sm+128; float* vp=sm+224; float* red=sm+480;
  int hh=lid&7, rloc=lid>>3, b=r0+rloc;
  int tid=threadIdx.x;
  int lens=*((volatile int*)&g_lens[b]);
  int p=min(max(lens-1,0),NT-1);
  size_t base=((((size_t)layer*NB+b)*NH+hh)*(size_t)NT)*HDIM;
  if(tid<192){
    int sec=tid>>6, d=tid&63;
    int col=sec*ND+hh*HDIM+d;
    float s=__ldg(&qb[col]);
    #pragma unroll
    for(int ch=0;ch<16;ch++) s+=__ldcv(&g_pQ[((size_t)ch*NB+b)*(3*ND)+col]);
    if(sec==0) qs[d]=s;
    else if(sec==1) g_K[base+(size_t)p*HDIM+d]=s;
    else           g_V[base+(size_t)p*HDIM+d]=s;
  }
  __syncthreads();
  int nk=p+1;
  if(tid<nk){
    const float* Kr=&g_K[base+(size_t)tid*HDIM];
    float s=0.f;
    #pragma unroll 16
    for(int d=0;d<HDIM;d++) s+=qs[d]*Kr[d];
    sc[tid]=s*0.125f;
  }
  __syncthreads();
  float m=(tid<nk)?sc[tid]:-3.4e38f;
  m=blockReduceMax(m,red);
  float e=0.f;
  if(tid<nk){ e=expf(sc[tid]-m); sc[tid]=e; }
  float sum=blockReduceSum(e,red);
  float inv=1.f/sum;
  {
    int d=tid&63, ks=tid>>6;
    float part=0.f;
    #pragma unroll 4
    for(int k=ks;k<nk;k+=4) part+=sc[k]*g_V[base+(size_t)k*HDIM+d];
    vp[ks*64+d]=part;
  }
  __syncthreads();
  if(tid<HDIM) os[tid]=(vp[tid]+vp[64+tid]+vp[128+tid]+vp[192+tid])*inv;
  __syncthreads();
  if(tid<128){
    int col=tid*4;
    float4 acc={0,0,0,0};
    const float4* Wp=(const float4*)(aw+(size_t)(hh*HDIM)*ND+col);
    const int str=ND/4;
    #pragma unroll
    for(int t2=0;t2<4;t2++){
      float4 wb[16];
      #pragma unroll
      for(int u=0;u<16;u++) wb[u]=__ldg(Wp+u*str);
      Wp+=16*str;
      #pragma unroll
      for(int u=0;u<16;u++){
        float o=os[t2*16+u];
        acc.x+=o*wb[u].x; acc.y+=o*wb[u].y; acc.z+=o*wb[u].z; acc.w+=o*wb[u].w;
      }
    }
    *(float4*)&g_pAO[((size_t)hh*NB+b)*ND+col]=acc;
  }
  __syncthreads();
}

// S2b LN2 mini-stage: 4 blocks/group: ao-reduce+residual(xA->xB)+LN2 -> g_h2
__device__ __forceinline__ void st_ln2_g(int b,const float* ab,
                                         const float* l2w,const float* l2b,float* sm){
  float* red=sm+9216;
  int tid=threadIdx.x;
  float v[2]; float s=0.f,s2=0.f;
  #pragma unroll
  for(int j=0;j<2;j++){
    int d=tid+j*256;
    float t=__ldcv(&g_xA[b*ND+d])+__ldg(&ab[d]);
    #pragma unroll
    for(int h=0;h<NH;h++) t+=__ldcv(&g_pAO[((size_t)h*NB+b)*ND+d]);
    g_xB[b*ND+d]=t;
    v[j]=t; s+=t; s2+=t*t;
  }
  s=blockReduceSum(s,red); s2=blockReduceSum(s2,red);
  float mean=s/(float)ND, var=s2/(float)ND-mean*mean;
  float rstd=1.f/sqrtf(var+1e-5f);
  #pragma unroll
  for(int j=0;j<2;j++){
    int d=tid+j*256;
    g_h2[b*ND+d]=(v[j]-mean)*rstd*__ldg(&l2w[d])+__ldg(&l2b[d]);
  }
}

// S3 fc: cb=lid&1 (2 x 1024 cols), ch=lid>>1 (16 x 32 k). batched prefetch.
__device__ __forceinline__ void st_fc_g(int r0,int lid,const float* W,float* sm){
  float* xs=sm;  // [32][4]
  int tid=threadIdx.x;
  int cb=lid&1, ch=lid>>1;
  int k0=ch*32;
  if(tid<128){
    int r=tid&3, kk=tid>>2;
    xs[kk*4+r]=__ldcv(&g_h2[(r0+r)*ND + k0+kk]);
  }
  __syncthreads();
  {
    int col=cb*1024+tid*4;
    float4 a0={0,0,0,0},a1={0,0,0,0},a2={0,0,0,0},a3={0,0,0,0};
    const float4* Wp=(const float4*)(W+(size_t)k0*NFF+col);
    const int str=NFF/4;
    #pragma unroll
    for(int t2=0;t2<2;t2++){
      float4 wb[16];
      #pragma unroll
      for(int u=0;u<16;u++) wb[u]=__ldg(Wp+u*str);
      Wp+=16*str;
      #pragma unroll
      for(int u=0;u<16;u++){
        float4 xv=*(const float4*)&xs[(t2*16+u)*4];
        FMA4(wb[u],xv)
      }
    }
    *(float4*)&g_pFC[((size_t)ch*NB+(r0+0))*NFF+col]=a0;
    *(float4*)&g_pFC[((size_t)ch*NB+(r0+1))*NFF+col]=a1;
    *(float4*)&g_pFC[((size_t)ch*NB+(r0+2))*NFF+col]=a2;
    *(float4*)&g_pFC[((size_t)ch*NB+(r0+3))*NFF+col]=a3;
  }
  __syncthreads();
}

// S4 pr: ch=lid (32 chunks x 64 k = 2048). batched prefetch.
__device__ __forceinline__ void st_pr_g(int r0,int lid,const float* fb,
                                        const float* W,float* sm){
  float* xs=sm;  // [64][4]
  int tid=threadIdx.x;
  int ch=lid;
  int k0=ch*64;
  {
    int r=tid&3, kk=tid>>2;   // 256 threads -> kk 0..63, r 0..3
    int n=k0+kk;
    float s=__ldg(&fb[n]);
    #pragma unroll
    for(int c=0;c<16;c++) s+=__ldcv(&g_pFC[((size_t)c*NB+(r0+r))*NFF+n]);
    xs[kk*4+r]=geluf(s);
  }
  __syncthreads();
  if(tid<128){
    int col=tid*4;
    float4 a0={0,0,0,0},a1={0,0,0,0},a2={0,0,0,0},a3={0,0,0,0};
    const float4* Wp=(const float4*)(W+(size_t)k0*ND+col);
    const int str=ND/4;
    #pragma unroll
    for(int t2=0;t2<4;t2++){
      float4 wb[16];
      #pragma unroll
      for(int u=0;u<16;u++) wb[u]=__ldg(Wp+u*str);
      Wp+=16*str;
      #pragma unroll
      for(int u=0;u<16;u++){
        float4 xv=*(const float4*)&xs[(t2*16+u)*4];
        FMA4(wb[u],xv)
      }
    }
    *(float4*)&g_pPR[((size_t)ch*NB+(r0+0))*ND+col]=a0;
    *(float4*)&g_pPR[((size_t)ch*NB+(r0+1))*ND+col]=a1;
    *(float4*)&g_pPR[((size_t)ch*NB+(r0+2))*ND+col]=a2;
    *(float4*)&g_pPR[((size_t)ch*NB+(r0+3))*ND+col]=a3;
  }
  __syncthreads();
}

// S5 redln: pr-reduce + residual(xB->xA) + LN -> dst. 4 blocks/group
__device__ __forceinline__ void st_redln_g(int b,const float* bias,
                                           const float* lnw,const float* lnb,
                                           float* dst,float* sm){
  float* red=sm+9216;
  int tid=threadIdx.x;
  float v[2]; float s=0.f,s2=0.f;
  #pragma unroll
  for(int j=0;j<2;j++){
    int d=tid+j*256;
    float t=__ldcv(&g_xB[b*ND+d])+__ldg(&bias[d]);
    #pragma unroll
    for(int ch=0;ch<32;ch++) t+=__ldcv(&g_pPR[((size_t)ch*NB+b)*ND+d]);
    g_xA[b*ND+d]=t;
    v[j]=t; s+=t; s2+=t*t;
  }
  s=blockReduceSum(s,red); s2=blockReduceSum(s2,red);
  float mean=s/(float)ND, var=s2/(float)ND-mean*mean;
  float rstd=1.f/sqrtf(var+1e-5f);
  #pragma unroll
  for(int j=0;j<2;j++){
    int d=tid+j*256;
    dst[b*ND+d]=(v[j]-mean)*rstd*__ldg(&lnw[d])+__ldg(&lnb[d]);
  }
}

// S6 lm: cb=lid&7 (8 x 1000 cols), ch=lid>>3 (4 x 128 k). batched prefetch.
__device__ __forceinline__ void st_lm_g(int r0,int lid,const float* lmw,float* sm){
  float* xs=sm;  // [128][4]
  int tid=threadIdx.x;
  int cb=lid&7, ch=lid>>3;
  int k0=ch*128;
  for(int i=tid;i<512;i+=256){
    int r=i&3, kk=i>>2;
    xs[kk*4+r]=__ldcv(&g_lnf16[(size_t)(r0+r)*ND+k0+kk]);
  }
  __syncthreads();
  if(tid<250){
    int col=(cb*250+tid)*4;
    float4 a0={0,0,0,0},a1={0,0,0,0},a2={0,0,0,0},a3={0,0,0,0};
    const float4* Wp=(const float4*)(lmw+(size_t)k0*NV+col);
    const int str=NV/4;
    #pragma unroll
    for(int t2=0;t2<8;t2++){
      float4 wb[16];
      #pragma unroll
      for(int u=0;u<16;u++) wb[u]=__ldg(Wp+u*str);
      Wp+=16*str;
      #pragma unroll
      for(int u=0;u<16;u++){
        float4 xv=*(const float4*)&xs[(t2*16+u)*4];
        FMA4(wb[u],xv)
      }
    }
    *(float4*)&g_pLM[((size_t)ch*NB+(r0+0))*NV+col]=a0;
    *(float4*)&g_pLM[((size_t)ch*NB+(r0+1))*NV+col]=a1;
    *(float4*)&g_pLM[((size_t)ch*NB+(r0+2))*NV+col]=a2;
    *(float4*)&g_pLM[((size_t)ch*NB+(r0+3))*NV+col]=a3;
  }
  __syncthreads();
}

// S7 sampler + fused embed+LN1 for next step
__device__ __forceinline__ void st_sampler_embed(int b,int step,float* out,
    const float* wte,const float* wpe,const float* lnw,const float* lnb,
    int do_embed,float* sm){
  float* lg=sm;
  float* shv=sm+8000;
  int*   shi=(int*)(sm+8256);
  float* red=sm+8512;
  int tid=threadIdx.x;
  float mv=-3.4e38f; int mi=NV;
  for(int i=tid;i<NV;i+=256){
    float v=__ldcv(&g_pLM[(size_t)b*NV+i])
          + __ldcv(&g_pLM[((size_t)NB+b)*NV+i])
          + __ldcv(&g_pLM[((size_t)2*NB+b)*NV+i])
          + __ldcv(&g_pLM[((size_t)3*NB+b)*NV+i]);
    lg[i]=v;
    if(v>mv){mv=v;mi=i;}
  }
  shv[tid]=mv; shi[tid]=mi;
  __syncthreads();
  for(int s=128;s>0;s>>=1){
    if(tid<s){
      if(shv[tid+s]>shv[tid] || (shv[tid+s]==shv[tid] && shi[tid+s]<shi[tid])){
        shv[tid]=shv[tid+s]; shi[tid]=shi[tid+s];
      }
    }
    __syncthreads();
  }
  float maxl=shv[0]; int top=shi[0];
  float sum=0.f;
  for(int i=tid;i<NV;i+=256) sum+=expf(lg[i]-maxl);
  sum=blockReduceSum(sum,red);
  if(tid==0){
    float topp=1.f/sum;
    int lens=g_lens[b], fin=g_fin[b];
    int active=(!fin)&&(lens<NT);
    if(active){g_csum[b]+=topp; g_ccnt[b]+=1.f;}
    int isend=(top==3)||(top==0);
    int write=active&&(!isend);
    int pos=min(max(lens,0),NT-1);
    if(write){g_ids[b*NT+pos]=top; g_lens[b]=lens+1;}
    if(active&&isend) g_fin[b]=1;
    out[b*NNEW+step]=write?(float)top:0.0f;
    if(step==NNEW-1){
      float cc=g_ccnt[b];
      out[NB*NNEW+b]=g_csum[b]/fmaxf(cc,1.f);
    }
  }
  __syncthreads();
  if(do_embed){
    int lens2=*((volatile int*)&g_lens[b]);
    int p=min(max(lens2-1,0),NT-1);
    int id=*((volatile int*)&g_ids[b*NT+p]);
    float v[2]; float s=0.f,s2=0.f;
    #pragma unroll
    for(int j=0;j<2;j++){
      int d=tid+j*256;
      float t=__ldg(&wte[(size_t)id*ND+d])+__ldg(&wpe[(size_t)p*ND+d]);
      g_xA[b*ND+d]=t;
      v[j]=t; s+=t; s2+=t*t;
    }
    s=blockReduceSum(s,red); s2=blockReduceSum(s2,red);
    float mean=s/(float)ND, var=s2/(float)ND-mean*mean;
    float rstd=1.f/sqrtf(var+1e-5f);
    #pragma unroll
    for(int j=0;j<2;j++){
      int d=tid+j*256;
      g_h16[b*ND+d]=(v[j]-mean)*rstd*__ldg(&lnw[d])+__ldg(&lnb[d]);
    }
  }
  __syncthreads();
}

// ------------------------- decode megakernel (4 independent groups) -------------------------
__global__ void __launch_bounds__(256,1) k_mega(
    const float* __restrict__ wte, const float* __restrict__ wpe,
    const float* __restrict__ ln1_w, const float* __restrict__ ln1_b,
    const float* __restrict__ qkv_w, const float* __restrict__ qkv_b,
    const float* __restrict__ ao_w,  const float* __restrict__ ao_b,
    const float* __restrict__ ln2_w, const float* __restrict__ ln2_b,
    const float* __restrict__ fc_w,  const float* __restrict__ fc_b,
    const float* __restrict__ pr_w,  const float* __restrict__ pr_b,
    const float* __restrict__ lnf_w, const float* __restrict__ lnf_b,
    const float* __restrict__ lm_w,  float* __restrict__ out){
  __shared__ float sm[9472];
  unsigned int gen=0;
  int bid=blockIdx.x;
  int g=bid>>5, lid=bid&31;
  int r0=g*RPG;

  st_lm_g(r0, lid, lm_w, sm);
  gsyncg(g, gen);
  if(lid<RPG) st_sampler_embed(r0+lid, 0, out, wte, wpe, ln1_w, ln1_b, 1, sm);
  gsyncg(g, gen);

  for(int s=1;s<NNEW;s++){
    for(int l=0;l<NL;l++){
      const float* qw=qkv_w+(size_t)l*ND*3*ND; const float* qb=qkv_b+(size_t)l*3*ND;
      const float* aw=ao_w +(size_t)l*ND*ND;   const float* ab=ao_b +(size_t)l*ND;
      const float* l2w=ln2_w+(size_t)l*ND;     const float* l2b=ln2_b+(size_t)l*ND;
      const float* fw=fc_w +(size_t)l*ND*NFF;  const float* fb=fc_b +(size_t)l*NFF;
      const float* pw=pr_w +(size_t)l*NFF*ND;  const float* pb=pr_b +(size_t)l*ND;

      st_qkv_g(r0, lid, qw, sm);
      gsyncg(g, gen);
      st_attn_g(r0, lid, l, qb, aw, sm);
      gsyncg(g, gen);
      if(lid<RPG) st_ln2_g(r0+lid, ab, l2w, l2b, sm);
      gsyncg(g, gen);
      st_fc_g(r0, lid, fw, sm);
      gsyncg(g, gen);
      st_pr_g(r0, lid, fb, pw, sm);
      gsyncg(g, gen);
      if(lid<RPG){
        if(l<NL-1) st_redln_g(r0+lid, pb, ln1_w+(size_t)(l+1)*ND, ln1_b+(size_t)(l+1)*ND, g_h16, sm);
        else       st_redln_g(r0+lid, pb, lnf_w, lnf_b, g_lnf16, sm);
      }
      gsyncg(g, gen);
    }
    st_lm_g(r0, lid, lm_w, sm);
    gsyncg(g, gen);
    if(lid<RPG) st_sampler_embed(r0+lid, s, out, wte, wpe, ln1_w, ln1_b, (s<NNEW-1)?1:0, sm);
    gsyncg(g, gen);
  }
}

// ------------------------- host launch -------------------------
extern "C" void kernel_launch(void* const* d_in, const int* in_sizes, int n_in,
                              void* d_out, int out_size) {
  const float* wte   =(const float*)d_in[0];
  const float* wpe   =(const float*)d_in[1];
  const float* ln1_w =(const float*)d_in[2];
  const float* ln1_b =(const float*)d_in[3];
  const float* qkv_w =(const float*)d_in[4];
  const float* qkv_b =(const float*)d_in[5];
  const float* ao_w  =(const float*)d_in[6];
  const float* ao_b  =(const float*)d_in[7];
  const float* ln2_w =(const float*)d_in[8];
  const float* ln2_b =(const float*)d_in[9];
  const float* fc_w  =(const float*)d_in[10];
  const float* fc_b  =(const float*)d_in[11];
  const float* pr_w  =(const float*)d_in[12];
  const float* pr_b  =(const float*)d_in[13];
  const float* lnf_w =(const float*)d_in[14];
  const float* lnf_b =(const float*)d_in[15];
  const float* lm_w  =(const float*)d_in[16];
  const int*   ids   =(const int*)d_in[17];
  const int*   mask  =(const int*)d_in[18];
  float* out=(float*)d_out;

  float *px,*ph,*pqkv,*pattn,*pff,*pxA,*plnf16;
  cudaGetSymbolAddress((void**)&px,     g_x);
  cudaGetSymbolAddress((void**)&ph,     g_h);
  cudaGetSymbolAddress((void**)&pqkv,   g_qkv);
  cudaGetSymbolAddress((void**)&pattn,  g_attn);
  cudaGetSymbolAddress((void**)&pff,    g_ff);
  cudaGetSymbolAddress((void**)&pxA,    g_xA);
  cudaGetSymbolAddress((void**)&plnf16, g_lnf16);

  k_init<<<1,256>>>(ids, mask);
  k_embed_pre<<<dim3(NPR,NB),256>>>(wte,wpe);

  // ---------- prefill (64x128 tiles) ----------
  for(int l=0;l<NL;l++){
    const float* l1w=ln1_w+l*ND;       const float* l1b=ln1_b+l*ND;
    const float* qw =qkv_w+(size_t)l*ND*3*ND; const float* qb =qkv_b+l*3*ND;
    const float* aw =ao_w +(size_t)l*ND*ND;   const float* ab =ao_b +l*ND;
    const float* l2w=ln2_w+l*ND;       const float* l2b=ln2_b+l*ND;
    const float* fw =fc_w +(size_t)l*ND*NFF;  const float* fb =fc_b +l*NFF;
    const float* pw =pr_w +(size_t)l*NFF*ND;  const float* pb =pr_b +l*ND;

    k_ln<<<NROWS,256>>>(px,ph,l1w,l1b);
    k_gemm<0><<<dim3(3*ND/128,NROWS/64),128>>>(ph,qw,qb,pqkv,nullptr,NROWS,3*ND,ND);
    k_attn_pre<<<dim3(NH,NB),256>>>(l);
    k_gemm<1><<<dim3(ND/128,NROWS/64),128>>>(pattn,aw,ab,px,px,NROWS,ND,ND);
    k_ln<<<NROWS,256>>>(px,ph,l2w,l2b);
    k_gemm<2><<<dim3(NFF/128,NROWS/64),128>>>(ph,fw,fb,pff,nullptr,NROWS,NFF,ND);
    k_gemm<1><<<dim3(ND/128,NROWS/64),128>>>(pff,pw,pb,px,px,NROWS,ND,NFF);
  }
  k_gather_last<<<NB,256>>>();
  k_ln<<<NB,256>>>(pxA,plnf16,lnf_w,lnf_b);

  // ---------- decode: one persistent kernel, 4 row-groups (R12) ----------
  k_mega<<<NBLK,256>>>(wte,wpe,ln1_w,ln1_b,qkv_w,qkv_b,ao_w,ao_b,
                       ln2_w,ln2_b,fc_w,fc_b,pr_w,pr_b,lnf_w,lnf_b,lm_w,out);
}

// round 17
// speedup vs baseline: 1.2158x; 1.2158x over previous
#include <cuda_runtime.h>
#include <math.h>

#define NL 8
#define NB 16
#define NT 80
#define ND 512
#define NH 8
#define HDIM 64
#define NV 8000
#define NPR 64
#define NNEW 16
#define NFF 2048
#define NROWS (NB*NPR)
#define NBLK 128
#define NGRP 4
#define GBLK 32
#define RPG 4

// ------------------------- device state -------------------------
__device__ float g_x[NROWS*ND];
__device__ float g_h[NROWS*ND];
__device__ float g_qkv[NROWS*3*ND];
__device__ float g_attn[NROWS*ND];
__device__ float g_ff[NROWS*NFF];
__device__ float g_gp[4*NROWS*ND];      // split-K partials for pr prefill gemm
__device__ float g_K[NL*NB*NH*NT*HDIM];
__device__ float g_V[NL*NB*NH*NT*HDIM];
__device__ float g_xA[NB*ND];
__device__ float g_xB[NB*ND];
__device__ float g_h16[NB*ND];          // LN1 output
__device__ float g_h2[NB*ND];           // LN2 output
__device__ float g_lnf16[NB*ND];
__device__ float g_pQ[16*NB*3*ND];      // qkv partials: 16 kchunks of 32
__device__ float g_pAO[NH*NB*ND];       // per-head ao partials
__device__ float g_pFC[16*NB*NFF];      // fc partials: 16 kchunks of 32
__device__ float g_pPR[32*NB*ND];       // pr partials: 32 kchunks of 64
__device__ float g_pLM[4*NB*NV];        // lm partials: 4 kchunks of 128
__device__ int   g_ids[NB*NT];
__device__ int   g_lens[NB];
__device__ int   g_fin[NB];
__device__ float g_csum[NB];
__device__ float g_ccnt[NB];
__device__ unsigned int g_garr[NGRP*32];
__device__ unsigned int g_grel[NGRP*32];

// ------------------------- helpers -------------------------
__device__ __forceinline__ float warpReduceSum(float v){
  #pragma unroll
  for(int o=16;o>0;o>>=1) v += __shfl_xor_sync(0xffffffffu, v, o);
  return v;
}
__device__ __forceinline__ float warpReduceMax(float v){
  #pragma unroll
  for(int o=16;o>0;o>>=1) v = fmaxf(v, __shfl_xor_sync(0xffffffffu, v, o));
  return v;
}
__device__ __forceinline__ float blockReduceSum(float v, float* sh){
  int tid=threadIdx.x;
  v = warpReduceSum(v);
  if((tid&31)==0) sh[tid>>5]=v;
  __syncthreads();
  int nw=(blockDim.x+31)>>5;
  float r = (tid < nw)? sh[tid] : 0.f;
  if (tid<32) r = warpReduceSum(r);
  if (tid==0) sh[0]=r;
  __syncthreads();
  r = sh[0];
  __syncthreads();
  return r;
}
__device__ __forceinline__ float blockReduceMax(float v, float* sh){
  int tid=threadIdx.x;
  v = warpReduceMax(v);
  if((tid&31)==0) sh[tid>>5]=v;
  __syncthreads();
  int nw=(blockDim.x+31)>>5;
  float r = (tid < nw)? sh[tid] : -3.4e38f;
  if (tid<32) r = warpReduceMax(r);
  if (tid==0) sh[0]=r;
  __syncthreads();
  r = sh[0];
  __syncthreads();
  return r;
}
__device__ __forceinline__ float geluf(float x){
  float x3=x*x*x;
  return 0.5f*x*(1.f+tanhf(0.7978845608028654f*(x+0.044715f*x3)));
}
__device__ __forceinline__ void gsyncg(int g, unsigned int &gen){
  __syncthreads();
  if(threadIdx.x==0){
    gen += 1u;
    __threadfence();
    unsigned int old=atomicAdd(&g_garr[g*32],1u);
    if(old == gen*GBLK - 1u){
      *((volatile unsigned int*)&g_grel[g*32]) = gen;
      __threadfence();
    }else{
      while(*((volatile unsigned int*)&g_grel[g*32]) < gen) {}
    }
    __threadfence();
  }
  __syncthreads();
}

// ------------------------- setup -------------------------
__global__ void k_init(const int* __restrict__ ids, const int* __restrict__ mask){
  int tid=threadIdx.x;
  if(tid<NGRP){ g_garr[tid*32]=0u; g_grel[tid*32]=0u; }
  for(int i=tid;i<NB*NT;i+=blockDim.x) g_ids[i]=ids[i];
  if(tid<NB){
    int s=0;
    for(int t=0;t<NT;t++) s += (mask[tid*NT+t]>0)?1:0;
    g_lens[tid]=s; g_fin[tid]=0; g_csum[tid]=0.f; g_ccnt[tid]=0.f;
  }
}

__global__ void k_embed_pre(const float* __restrict__ wte, const float* __restrict__ wpe){
  int p=blockIdx.x, b=blockIdx.y;
  int id=g_ids[b*NT+p];
  int row=b*NPR+p;
  for(int d=threadIdx.x; d<ND; d+=blockDim.x)
    g_x[(size_t)row*ND+d] = wte[(size_t)id*ND+d] + wpe[(size_t)p*ND+d];
}

__global__ void k_ln(const float* __restrict__ X, float* __restrict__ Y,
                     const float* __restrict__ w, const float* __restrict__ bb){
  __shared__ float sh[32];
  int r=blockIdx.x;
  const float* x=X+(size_t)r*ND;
  float s=0.f,s2=0.f;
  for(int i=threadIdx.x;i<ND;i+=blockDim.x){float v=x[i]; s+=v; s2+=v*v;}
  s  = blockReduceSum(s, sh);
  s2 = blockReduceSum(s2, sh);
  float mean=s/(float)ND;
  float var=s2/(float)ND-mean*mean;
  float rstd=1.f/sqrtf(var+1e-5f);
  for(int i=threadIdx.x;i<ND;i+=blockDim.x){
    float v=x[i];
    Y[(size_t)r*ND+i]=(v-mean)*rstd*w[i]+bb[i];
  }
}

// ------------------------- prefill kernels -------------------------
// double-buffered (R12 version)
template<int EPI>
__global__ void k_gemm(const float* __restrict__ A, const float* __restrict__ W,
                       const float* __restrict__ bias, float* __restrict__ C,
                       const float* __restrict__ R, int M, int N, int K){
  __shared__ float As[64*16];
  __shared__ float Ws[16*64];
  int tid=threadIdx.x;
  int tx=tid&15, ty=tid>>4;
  int row0=blockIdx.y*64, col0=blockIdx.x*64;
  float acc[8][4];
  #pragma unroll
  for(int i=0;i<8;i++)
    #pragma unroll
    for(int j=0;j<4;j++) acc[i][j]=0.f;

  float ra[8], rw[8];
  #pragma unroll
  for(int i=0;i<8;i++){
    int idx=tid+i*128;
    ra[i]=A[(size_t)(row0+(idx>>4))*K + (idx&15)];
    rw[i]=W[(size_t)(idx>>6)*N + col0+(idx&63)];
  }
  #pragma unroll
  for(int i=0;i<8;i++){
    int idx=tid+i*128;
    As[idx]=ra[i]; Ws[idx]=rw[i];
  }
  __syncthreads();

  for(int k0=16;k0<=K;k0+=16){
    bool more=(k0<K);
    if(more){
      #pragma unroll
      for(int i=0;i<8;i++){
        int idx=tid+i*128;
        ra[i]=A[(size_t)(row0+(idx>>4))*K + k0+(idx&15)];
        rw[i]=W[(size_t)(k0+(idx>>6))*N + col0+(idx&63)];
      }
    }
    #pragma unroll
    for(int kk=0;kk<16;kk++){
      float a[8], wv[4];
      #pragma unroll
      for(int i=0;i<8;i++) a[i]=As[(ty*8+i)*16+kk];
      #pragma unroll
      for(int j=0;j<4;j++) wv[j]=Ws[kk*64+tx*4+j];
      #pragma unroll
      for(int i=0;i<8;i++)
        #pragma unroll
        for(int j=0;j<4;j++)
          acc[i][j] += a[i]*wv[j];
    }
    __syncthreads();
    if(more){
      #pragma unroll
      for(int i=0;i<8;i++){
        int idx=tid+i*128;
        As[idx]=ra[i]; Ws[idx]=rw[i];
      }
    }
    __syncthreads();
  }
  #pragma unroll
  for(int i=0;i<8;i++){
    int row=row0+ty*8+i;
    #pragma unroll
    for(int j=0;j<4;j++){
      int col=col0+tx*4+j;
      float v=acc[i][j]+bias[col];
      if(EPI==1) v += R[(size_t)row*N+col];
      if(EPI==2) v = geluf(v);
      C[(size_t)row*N+col]=v;
    }
  }
}

// split-K partial gemm for pr (K chunk of 512 per blockIdx.z); raw partials, no bias
#define KCH 512
__global__ void k_gemm_p(const float* __restrict__ A, const float* __restrict__ W,
                         int M, int N, int K){
  __shared__ float As[64*16];
  __shared__ float Ws[16*64];
  int tid=threadIdx.x;
  int tx=tid&15, ty=tid>>4;
  int row0=blockIdx.y*64, col0=blockIdx.x*64;
  int kz=blockIdx.z, kbase=kz*KCH;
  float acc[8][4];
  #pragma unroll
  for(int i=0;i<8;i++)
    #pragma unroll
    for(int j=0;j<4;j++) acc[i][j]=0.f;

  float ra[8], rw[8];
  #pragma unroll
  for(int i=0;i<8;i++){
    int idx=tid+i*128;
    ra[i]=A[(size_t)(row0+(idx>>4))*K + kbase+(idx&15)];
    rw[i]=W[(size_t)(kbase+(idx>>6))*N + col0+(idx&63)];
  }
  #pragma unroll
  for(int i=0;i<8;i++){
    int idx=tid+i*128;
    As[idx]=ra[i]; Ws[idx]=rw[i];
  }
  __syncthreads();

  for(int k0=16;k0<=KCH;k0+=16){
    bool more=(k0<KCH);
    if(more){
      #pragma unroll
      for(int i=0;i<8;i++){
        int idx=tid+i*128;
        ra[i]=A[(size_t)(row0+(idx>>4))*K + kbase+k0+(idx&15)];
        rw[i]=W[(size_t)(kbase+k0+(idx>>6))*N + col0+(idx&63)];
      }
    }
    #pragma unroll
    for(int kk=0;kk<16;kk++){
      float a[8], wv[4];
      #pragma unroll
      for(int i=0;i<8;i++) a[i]=As[(ty*8+i)*16+kk];
      #pragma unroll
      for(int j=0;j<4;j++) wv[j]=Ws[kk*64+tx*4+j];
      #pragma unroll
      for(int i=0;i<8;i++)
        #pragma unroll
        for(int j=0;j<4;j++)
          acc[i][j] += a[i]*wv[j];
    }
    __syncthreads();
    if(more){
      #pragma unroll
      for(int i=0;i<8;i++){
        int idx=tid+i*128;
        As[idx]=ra[i]; Ws[idx]=rw[i];
      }
    }
    __syncthreads();
  }
  float* outp=&g_gp[(size_t)kz*NROWS*ND];
  #pragma unroll
  for(int i=0;i<8;i++){
    int row=row0+ty*8+i;
    #pragma unroll
    for(int j=0;j<4;j++){
      int col=col0+tx*4+j;
      outp[(size_t)row*ND+col]=acc[i][j];
    }
  }
}

// reduce pr split-K partials + bias + residual into g_x
__global__ void k_redpr(const float* __restrict__ bias){
  int row=blockIdx.x, tid=threadIdx.x;
  #pragma unroll
  for(int j=0;j<2;j++){
    int d=tid+j*256;
    float v=g_x[(size_t)row*ND+d]+bias[d];
    #pragma unroll
    for(int z=0;z<4;z++) v+=g_gp[(size_t)z*NROWS*ND+(size_t)row*ND+d];
    g_x[(size_t)row*ND+d]=v;
  }
}

__global__ void k_attn_pre(int layer){
  __shared__ float Ks[64*65];
  __shared__ float Vs[64*65];
  __shared__ float qsm[8*64];
  __shared__ float psm[8*64];
  int hh=blockIdx.x, b=blockIdx.y;
  int tid=threadIdx.x;
  size_t base=((((size_t)layer*NB+b)*NH+hh)*(size_t)NT)*HDIM;
  for(int idx=tid; idx<64*64; idx+=256){
    int k=idx>>6, d=idx&63;
    size_t src=(size_t)(b*NPR+k)*3*ND + hh*HDIM + d;
    float kv=g_qkv[src+ND];
    float vv=g_qkv[src+2*ND];
    Ks[k*65+d]=kv; Vs[k*65+d]=vv;
    g_K[base+(size_t)k*HDIM+d]=kv;
    g_V[base+(size_t)k*HDIM+d]=vv;
  }
  __syncthreads();
  int w=tid>>5, lane=tid&31;
  for(int qi=0;qi<8;qi++){
    int p=w*8+qi;
    int row=b*NPR+p;
    const float* qp=&g_qkv[(size_t)row*3*ND + hh*HDIM];
    qsm[w*64+lane]=qp[lane];
    qsm[w*64+lane+32]=qp[lane+32];
    __syncwarp();
    float s0=0.f,s1=0.f;
    #pragma unroll 8
    for(int d=0;d<64;d++){
      float qd=qsm[w*64+d];
      s0+=qd*Ks[lane*65+d];
      s1+=qd*Ks[(lane+32)*65+d];
    }
    s0 = s0*0.125f + ((lane   <=p)?0.f:-1e9f);
    s1 = s1*0.125f + ((lane+32<=p)?0.f:-1e9f);
    float m = warpReduceMax(fmaxf(s0,s1));
    float e0=expf(s0-m), e1=expf(s1-m);
    float sum=warpReduceSum(e0+e1);
    float inv=1.f/sum;
    psm[w*64+lane]=e0*inv;
    psm[w*64+lane+32]=e1*inv;
    __syncwarp();
    float o0=0.f,o1=0.f;
    #pragma unroll 8
    for(int k=0;k<64;k++){
      float pk=psm[w*64+k];
      o0+=pk*Vs[k*65+lane];
      o1+=pk*Vs[k*65+lane+32];
    }
    g_attn[(size_t)row*ND+hh*HDIM+lane]   =o0;
    g_attn[(size_t)row*ND+hh*HDIM+lane+32]=o1;
    __syncwarp();
  }
}

__global__ void k_gather_last(){
  int b=blockIdx.x;
  int p=min(max(g_lens[b]-1,0),NPR-1);
  for(int d=threadIdx.x; d<ND; d+=blockDim.x)
    g_xA[(size_t)b*ND+d]=g_x[(size_t)(b*NPR+p)*ND+d];
}

// ------------------------- group decode stages (R12, NGRP=4) -------------------------
#define FMA4(wv,xv) \
  a0.x+=xv.x*wv.x; a0.y+=xv.x*wv.y; a0.z+=xv.x*wv.z; a0.w+=xv.x*wv.w; \
  a1.x+=xv.y*wv.x; a1.y+=xv.y*wv.y; a1.z+=xv.y*wv.z; a1.w+=xv.y*wv.w; \
  a2.x+=xv.z*wv.x; a2.y+=xv.z*wv.y; a2.z+=xv.z*wv.z; a2.w+=xv.z*wv.w; \
  a3.x+=xv.w*wv.x; a3.y+=xv.w*wv.y; a3.z+=xv.w*wv.z; a3.w+=xv.w*wv.w;

// S1 qkv: cb=lid&1 (2 x 768 cols), ch=lid>>1 (16 x 32 k). batched prefetch.
__device__ __forceinline__ void st_qkv_g(int r0,int lid,const float* W,float* sm){
  float* xs=sm;  // [32][4]
  int tid=threadIdx.x;
  int cb=lid&1, ch=lid>>1;
  int k0=ch*32;
  if(tid<128){
    int r=tid&3, kk=tid>>2;
    xs[kk*4+r]=__ldcv(&g_h16[(r0+r)*ND + k0+kk]);
  }
  __syncthreads();
  if(tid<192){
    int col=cb*768+tid*4;
    float4 a0={0,0,0,0},a1={0,0,0,0},a2={0,0,0,0},a3={0,0,0,0};
    const float4* Wp=(const float4*)(W+(size_t)k0*(3*ND)+col);
    const int str=(3*ND)/4;
    #pragma unroll
    for(int t2=0;t2<2;t2++){
      float4 wb[16];
      #pragma unroll
      for(int u=0;u<16;u++) wb[u]=__ldg(Wp+u*str);
      Wp+=16*str;
      #pragma unroll
      for(int u=0;u<16;u++){
        float4 xv=*(const float4*)&xs[(t2*16+u)*4];
        FMA4(wb[u],xv)
      }
    }
    *(float4*)&g_pQ[((size_t)ch*NB+(r0+0))*(3*ND)+col]=a0;
    *(float4*)&g_pQ[((size_t)ch*NB+(r0+1))*(3*ND)+col]=a1;
    *(float4*)&g_pQ[((size_t)ch*NB+(r0+2))*(3*ND)+col]=a2;
    *(float4*)&g_pQ[((size_t)ch*NB+(r0+3))*(3*ND)+col]=a3;
  }
  __syncthreads();
}

// S2 attn: 32 tasks (4 rows x 8 heads)
__device__ __forceinline__ void st_attn_g(int r0,int lid,int layer,const float* qb,
                                          const float* aw,float* sm){
  float* qs=sm; float* os=sm+64; float* sc=sm+128; float* vp=sm+224; float* red=sm+480;
  int hh=lid&7, rloc=lid>>3, b=r0+rloc;
  int tid=threadIdx.x;
  int lens=*((volatile int*)&g_lens[b]);
  int p=min(max(lens-1,0),NT-1);
  size_t base=((((size_t)layer*NB+b)*NH+hh)*(size_t)NT)*HDIM;
  if(tid<192){
    int sec=tid>>6, d=tid&63;
    int col=sec*ND+hh*HDIM+d;
    float s=__ldg(&qb[col]);
    #pragma unroll
    for(int ch=0;ch<16;ch++) s+=__ldcv(&g_pQ[((size_t)ch*NB+b)*(3*ND)+col]);
    if(sec==0) qs[d]=s;
    else if(sec==1) g_K[base+(size_t)p*HDIM+d]=s;
    else           g_V[base+(size_t)p*HDIM+d]=s;
  }
  __syncthreads();
  int nk=p+1;
  if(tid<nk){
    const float* Kr=&g_K[base+(size_t)tid*HDIM];
    float s=0.f;
    #pragma unroll 16
    for(int d=0;d<HDIM;d++) s+=qs[d]*Kr[d];
    sc[tid]=s*0.125f;
  }
  __syncthreads();
  float m=(tid<nk)?sc[tid]:-3.4e38f;
  m=blockReduceMax(m,red);
  float e=0.f;
  if(tid<nk){ e=expf(sc[tid]-m); sc[tid]=e; }
  float sum=blockReduceSum(e,red);
  float inv=1.f/sum;
  {
    int d=tid&63, ks=tid>>6;
    float part=0.f;
    #pragma unroll 4
    for(int k=ks;k<nk;k+=4) part+=sc[k]*g_V[base+(size_t)k*HDIM+d];
    vp[ks*64+d]=part;
  }
  __syncthreads();
  if(tid<HDIM) os[tid]=(vp[tid]+vp[64+tid]+vp[128+tid]+vp[192+tid])*inv;
  __syncthreads();
  if(tid<128){
    int col=tid*4;
    float4 acc={0,0,0,0};
    const float4* Wp=(const float4*)(aw+(size_t)(hh*HDIM)*ND+col);
    const int str=ND/4;
    #pragma unroll
    for(int t2=0;t2<4;t2++){
      float4 wb[16];
      #pragma unroll
      for(int u=0;u<16;u++) wb[u]=__ldg(Wp+u*str);
      Wp+=16*str;
      #pragma unroll
      for(int u=0;u<16;u++){
        float o=os[t2*16+u];
        acc.x+=o*wb[u].x; acc.y+=o*wb[u].y; acc.z+=o*wb[u].z; acc.w+=o*wb[u].w;
      }
    }
    *(float4*)&g_pAO[((size_t)hh*NB+b)*ND+col]=acc;
  }
  __syncthreads();
}

// S2b LN2 mini-stage: 4 blocks/group: ao-reduce+residual(xA->xB)+LN2 -> g_h2
__device__ __forceinline__ void st_ln2_g(int b,const float* ab,
                                         const float* l2w,const float* l2b,float* sm){
  float* red=sm+9216;
  int tid=threadIdx.x;
  float v[2]; float s=0.f,s2=0.f;
  #pragma unroll
  for(int j=0;j<2;j++){
    int d=tid+j*256;
    float t=__ldcv(&g_xA[b*ND+d])+__ldg(&ab[d]);
    #pragma unroll
    for(int h=0;h<NH;h++) t+=__ldcv(&g_pAO[((size_t)h*NB+b)*ND+d]);
    g_xB[b*ND+d]=t;
    v[j]=t; s+=t; s2+=t*t;
  }
  s=blockReduceSum(s,red); s2=blockReduceSum(s2,red);
  float mean=s/(float)ND, var=s2/(float)ND-mean*mean;
  float rstd=1.f/sqrtf(var+1e-5f);
  #pragma unroll
  for(int j=0;j<2;j++){
    int d=tid+j*256;
    g_h2[b*ND+d]=(v[j]-mean)*rstd*__ldg(&l2w[d])+__ldg(&l2b[d]);
  }
}

// S3 fc: cb=lid&1 (2 x 1024 cols), ch=lid>>1 (16 x 32 k). batched prefetch.
__device__ __forceinline__ void st_fc_g(int r0,int lid,const float* W,float* sm){
  float* xs=sm;  // [32][4]
  int tid=threadIdx.x;
  int cb=lid&1, ch=lid>>1;
  int k0=ch*32;
  if(tid<128){
    int r=tid&3, kk=tid>>2;
    xs[kk*4+r]=__ldcv(&g_h2[(r0+r)*ND + k0+kk]);
  }
  __syncthreads();
  {
    int col=cb*1024+tid*4;
    float4 a0={0,0,0,0},a1={0,0,0,0},a2={0,0,0,0},a3={0,0,0,0};
    const float4* Wp=(const float4*)(W+(size_t)k0*NFF+col);
    const int str=NFF/4;
    #pragma unroll
    for(int t2=0;t2<2;t2++){
      float4 wb[16];
      #pragma unroll
      for(int u=0;u<16;u++) wb[u]=__ldg(Wp+u*str);
      Wp+=16*str;
      #pragma unroll
      for(int u=0;u<16;u++){
        float4 xv=*(const float4*)&xs[(t2*16+u)*4];
        FMA4(wb[u],xv)
      }
    }
    *(float4*)&g_pFC[((size_t)ch*NB+(r0+0))*NFF+col]=a0;
    *(float4*)&g_pFC[((size_t)ch*NB+(r0+1))*NFF+col]=a1;
    *(float4*)&g_pFC[((size_t)ch*NB+(r0+2))*NFF+col]=a2;
    *(float4*)&g_pFC[((size_t)ch*NB+(r0+3))*NFF+col]=a3;
  }
  __syncthreads();
}

// S4 pr: ch=lid (32 chunks x 64 k = 2048). batched prefetch.
__device__ __forceinline__ void st_pr_g(int r0,int lid,const float* fb,
                                        const float* W,float* sm){
  float* xs=sm;  // [64][4]
  int tid=threadIdx.x;
  int ch=lid;
  int k0=ch*64;
  {
    int r=tid&3, kk=tid>>2;   // 256 threads -> kk 0..63, r 0..3
    int n=k0+kk;
    float s=__ldg(&fb[n]);
    #pragma unroll
    for(int c=0;c<16;c++) s+=__ldcv(&g_pFC[((size_t)c*NB+(r0+r))*NFF+n]);
    xs[kk*4+r]=geluf(s);
  }
  __syncthreads();
  if(tid<128){
    int col=tid*4;
    float4 a0={0,0,0,0},a1={0,0,0,0},a2={0,0,0,0},a3={0,0,0,0};
    const float4* Wp=(const float4*)(W+(size_t)k0*ND+col);
    const int str=ND/4;
    #pragma unroll
    for(int t2=0;t2<4;t2++){
      float4 wb[16];
      #pragma unroll
      for(int u=0;u<16;u++) wb[u]=__ldg(Wp+u*str);
      Wp+=16*str;
      #pragma unroll
      for(int u=0;u<16;u++){
        float4 xv=*(const float4*)&xs[(t2*16+u)*4];
        FMA4(wb[u],xv)
      }
    }
    *(float4*)&g_pPR[((size_t)ch*NB+(r0+0))*ND+col]=a0;
    *(float4*)&g_pPR[((size_t)ch*NB+(r0+1))*ND+col]=a1;
    *(float4*)&g_pPR[((size_t)ch*NB+(r0+2))*ND+col]=a2;
    *(float4*)&g_pPR[((size_t)ch*NB+(r0+3))*ND+col]=a3;
  }
  __syncthreads();
}

// S5 redln: pr-reduce + residual(xB->xA) + LN -> dst. 4 blocks/group
__device__ __forceinline__ void st_redln_g(int b,const float* bias,
                                           const float* lnw,const float* lnb,
                                           float* dst,float* sm){
  float* red=sm+9216;
  int tid=threadIdx.x;
  float v[2]; float s=0.f,s2=0.f;
  #pragma unroll
  for(int j=0;j<2;j++){
    int d=tid+j*256;
    float t=__ldcv(&g_xB[b*ND+d])+__ldg(&bias[d]);
    #pragma unroll
    for(int ch=0;ch<32;ch++) t+=__ldcv(&g_pPR[((size_t)ch*NB+b)*ND+d]);
    g_xA[b*ND+d]=t;
    v[j]=t; s+=t; s2+=t*t;
  }
  s=blockReduceSum(s,red); s2=blockReduceSum(s2,red);
  float mean=s/(float)ND, var=s2/(float)ND-mean*mean;
  float rstd=1.f/sqrtf(var+1e-5f);
  #pragma unroll
  for(int j=0;j<2;j++){
    int d=tid+j*256;
    dst[b*ND+d]=(v[j]-mean)*rstd*__ldg(&lnw[d])+__ldg(&lnb[d]);
  }
}

// S6 lm: cb=lid&7 (8 x 1000 cols), ch=lid>>3 (4 x 128 k). batched prefetch.
__device__ __forceinline__ void st_lm_g(int r0,int lid,const float* lmw,float* sm){
  float* xs=sm;  // [128][4]
  int tid=threadIdx.x;
  int cb=lid&7, ch=lid>>3;
  int k0=ch*128;
  for(int i=tid;i<512;i+=256){
    int r=i&3, kk=i>>2;
    xs[kk*4+r]=__ldcv(&g_lnf16[(size_t)(r0+r)*ND+k0+kk]);
  }
  __syncthreads();
  if(tid<250){
    int col=(cb*250+tid)*4;
    float4 a0={0,0,0,0},a1={0,0,0,0},a2={0,0,0,0},a3={0,0,0,0};
    const float4* Wp=(const float4*)(lmw+(size_t)k0*NV+col);
    const int str=NV/4;
    #pragma unroll
    for(int t2=0;t2<8;t2++){
      float4 wb[16];
      #pragma unroll
      for(int u=0;u<16;u++) wb[u]=__ldg(Wp+u*str);
      Wp+=16*str;
      #pragma unroll
      for(int u=0;u<16;u++){
        float4 xv=*(const float4*)&xs[(t2*16+u)*4];
        FMA4(wb[u],xv)
      }
    }
    *(float4*)&g_pLM[((size_t)ch*NB+(r0+0))*NV+col]=a0;
    *(float4*)&g_pLM[((size_t)ch*NB+(r0+1))*NV+col]=a1;
    *(float4*)&g_pLM[((size_t)ch*NB+(r0+2))*NV+col]=a2;
    *(float4*)&g_pLM[((size_t)ch*NB+(r0+3))*NV+col]=a3;
  }
  __syncthreads();
}

// S7 sampler + fused embed+LN1 for next step
__device__ __forceinline__ void st_sampler_embed(int b,int step,float* out,
    const float* wte,const float* wpe,const float* lnw,const float* lnb,
    int do_embed,float* sm){
  float* lg=sm;
  float* shv=sm+8000;
  int*   shi=(int*)(sm+8256);
  float* red=sm+8512;
  int tid=threadIdx.x;
  float mv=-3.4e38f; int mi=NV;
  for(int i=tid;i<NV;i+=256){
    float v=__ldcv(&g_pLM[(size_t)b*NV+i])
          + __ldcv(&g_pLM[((size_t)NB+b)*NV+i])
          + __ldcv(&g_pLM[((size_t)2*NB+b)*NV+i])
          + __ldcv(&g_pLM[((size_t)3*NB+b)*NV+i]);
    lg[i]=v;
    if(v>mv){mv=v;mi=i;}
  }
  shv[tid]=mv; shi[tid]=mi;
  __syncthreads();
  for(int s=128;s>0;s>>=1){
    if(tid<s){
      if(shv[tid+s]>shv[tid] || (shv[tid+s]==shv[tid] && shi[tid+s]<shi[tid])){
        shv[tid]=shv[tid+s]; shi[tid]=shi[tid+s];
      }
    }
    __syncthreads();
  }
  float maxl=shv[0]; int top=shi[0];
  float sum=0.f;
  for(int i=tid;i<NV;i+=256) sum+=expf(lg[i]-maxl);
  sum=blockReduceSum(sum,red);
  if(tid==0){
    float topp=1.f/sum;
    int lens=g_lens[b], fin=g_fin[b];
    int active=(!fin)&&(lens<NT);
    if(active){g_csum[b]+=topp; g_ccnt[b]+=1.f;}
    int isend=(top==3)||(top==0);
    int write=active&&(!isend);
    int pos=min(max(lens,0),NT-1);
    if(write){g_ids[b*NT+pos]=top; g_lens[b]=lens+1;}
    if(active&&isend) g_fin[b]=1;
    out[b*NNEW+step]=write?(float)top:0.0f;
    if(step==NNEW-1){
      float cc=g_ccnt[b];
      out[NB*NNEW+b]=g_csum[b]/fmaxf(cc,1.f);
    }
  }
  __syncthreads();
  if(do_embed){
    int lens2=*((volatile int*)&g_lens[b]);
    int p=min(max(lens2-1,0),NT-1);
    int id=*((volatile int*)&g_ids[b*NT+p]);
    float v[2]; float s=0.f,s2=0.f;
    #pragma unroll
    for(int j=0;j<2;j++){
      int d=tid+j*256;
      float t=__ldg(&wte[(size_t)id*ND+d])+__ldg(&wpe[(size_t)p*ND+d]);
      g_xA[b*ND+d]=t;
      v[j]=t; s+=t; s2+=t*t;
    }
    s=blockReduceSum(s,red); s2=blockReduceSum(s2,red);
    float mean=s/(float)ND, var=s2/(float)ND-mean*mean;
    float rstd=1.f/sqrtf(var+1e-5f);
    #pragma unroll
    for(int j=0;j<2;j++){
      int d=tid+j*256;
      g_h16[b*ND+d]=(v[j]-mean)*rstd*__ldg(&lnw[d])+__ldg(&lnb[d]);
    }
  }
  __syncthreads();
}

// ------------------------- decode megakernel (4 independent groups) -------------------------
__global__ void __launch_bounds__(256,1) k_mega(
    const float* __restrict__ wte, const float* __restrict__ wpe,
    const float* __restrict__ ln1_w, const float* __restrict__ ln1_b,
    const float* __restrict__ qkv_w, const float* __restrict__ qkv_b,
    const float* __restrict__ ao_w,  const float* __restrict__ ao_b,
    const float* __restrict__ ln2_w, const float* __restrict__ ln2_b,
    const float* __restrict__ fc_w,  const float* __restrict__ fc_b,
    const float* __restrict__ pr_w,  const float* __restrict__ pr_b,
    const float* __restrict__ lnf_w, const float* __restrict__ lnf_b,
    const float* __restrict__ lm_w,  float* __restrict__ out){
  __shared__ float sm[9472];
  unsigned int gen=0;
  int bid=blockIdx.x;
  int g=bid>>5, lid=bid&31;
  int r0=g*RPG;

  st_lm_g(r0, lid, lm_w, sm);
  gsyncg(g, gen);
  if(lid<RPG) st_sampler_embed(r0+lid, 0, out, wte, wpe, ln1_w, ln1_b, 1, sm);
  gsyncg(g, gen);

  for(int s=1;s<NNEW;s++){
    for(int l=0;l<NL;l++){
      const float* qw=qkv_w+(size_t)l*ND*3*ND; const float* qb=qkv_b+(size_t)l*3*ND;
      const float* aw=ao_w +(size_t)l*ND*ND;   const float* ab=ao_b +(size_t)l*ND;
      const float* l2w=ln2_w+(size_t)l*ND;     const float* l2b=ln2_b+(size_t)l*ND;
      const float* fw=fc_w +(size_t)l*ND*NFF;  const float* fb=fc_b +(size_t)l*NFF;
      const float* pw=pr_w +(size_t)l*NFF*ND;  const float* pb=pr_b +(size_t)l*ND;

      st_qkv_g(r0, lid, qw, sm);
      gsyncg(g, gen);
      st_attn_g(r0, lid, l, qb, aw, sm);
      gsyncg(g, gen);
      if(lid<RPG) st_ln2_g(r0+lid, ab, l2w, l2b, sm);
      gsyncg(g, gen);
      st_fc_g(r0, lid, fw, sm);
      gsyncg(g, gen);
      st_pr_g(r0, lid, fb, pw, sm);
      gsyncg(g, gen);
      if(lid<RPG){
        if(l<NL-1) st_redln_g(r0+lid, pb, ln1_w+(size_t)(l+1)*ND, ln1_b+(size_t)(l+1)*ND, g_h16, sm);
        else       st_redln_g(r0+lid, pb, lnf_w, lnf_b, g_lnf16, sm);
      }
      gsyncg(g, gen);
    }
    st_lm_g(r0, lid, lm_w, sm);
    gsyncg(g, gen);
    if(lid<RPG) st_sampler_embed(r0+lid, s, out, wte, wpe, ln1_w, ln1_b, (s<NNEW-1)?1:0, sm);
    gsyncg(g, gen);
  }
}

// ------------------------- host launch -------------------------
extern "C" void kernel_launch(void* const* d_in, const int* in_sizes, int n_in,
                              void* d_out, int out_size) {
  const float* wte   =(const float*)d_in[0];
  const float* wpe   =(const float*)d_in[1];
  const float* ln1_w =(const float*)d_in[2];
  const float* ln1_b =(const float*)d_in[3];
  const float* qkv_w =(const float*)d_in[4];
  const float* qkv_b =(const float*)d_in[5];
  const float* ao_w  =(const float*)d_in[6];
  const float* ao_b  =(const float*)d_in[7];
  const float* ln2_w =(const float*)d_in[8];
  const float* ln2_b =(const float*)d_in[9];
  const float* fc_w  =(const float*)d_in[10];
  const float* fc_b  =(const float*)d_in[11];
  const float* pr_w  =(const float*)d_in[12];
  const float* pr_b  =(const float*)d_in[13];
  const float* lnf_w =(const float*)d_in[14];
  const float* lnf_b =(const float*)d_in[15];
  const float* lm_w  =(const float*)d_in[16];
  const int*   ids   =(const int*)d_in[17];
  const int*   mask  =(const int*)d_in[18];
  float* out=(float*)d_out;

  float *px,*ph,*pqkv,*pattn,*pff,*pxA,*plnf16;
  cudaGetSymbolAddress((void**)&px,     g_x);
  cudaGetSymbolAddress((void**)&ph,     g_h);
  cudaGetSymbolAddress((void**)&pqkv,   g_qkv);
  cudaGetSymbolAddress((void**)&pattn,  g_attn);
  cudaGetSymbolAddress((void**)&pff,    g_ff);
  cudaGetSymbolAddress((void**)&pxA,    g_xA);
  cudaGetSymbolAddress((void**)&plnf16, g_lnf16);

  k_init<<<1,256>>>(ids, mask);
  k_embed_pre<<<dim3(NPR,NB),256>>>(wte,wpe);

  // ---------- prefill ----------
  for(int l=0;l<NL;l++){
    const float* l1w=ln1_w+l*ND;       const float* l1b=ln1_b+l*ND;
    const float* qw =qkv_w+(size_t)l*ND*3*ND; const float* qb =qkv_b+l*3*ND;
    const float* aw =ao_w +(size_t)l*ND*ND;   const float* ab =ao_b +l*ND;
    const float* l2w=ln2_w+l*ND;       const float* l2b=ln2_b+l*ND;
    const float* fw =fc_w +(size_t)l*ND*NFF;  const float* fb =fc_b +l*NFF;
    const float* pw =pr_w +(size_t)l*NFF*ND;  const float* pb =pr_b +l*ND;

    k_ln<<<NROWS,256>>>(px,ph,l1w,l1b);
    k_gemm<0><<<dim3(3*ND/64,NROWS/64),128>>>(ph,qw,qb,pqkv,nullptr,NROWS,3*ND,ND);
    k_attn_pre<<<dim3(NH,NB),256>>>(l);
    k_gemm<1><<<dim3(ND/64,NROWS/64),128>>>(pattn,aw,ab,px,px,NROWS,ND,ND);
    k_ln<<<NROWS,256>>>(px,ph,l2w,l2b);
    k_gemm<2><<<dim3(NFF/64,NROWS/64),128>>>(ph,fw,fb,pff,nullptr,NROWS,NFF,ND);
    k_gemm_p<<<dim3(ND/64,NROWS/64,4),128>>>(pff,pw,NROWS,ND,NFF);
    k_redpr<<<NROWS,256>>>(pb);
  }
  k_gather_last<<<NB,256>>>();
  k_ln<<<NB,256>>>(pxA,plnf16,lnf_w,lnf_b);

  // ---------- decode: one persistent kernel, 4 row-groups (R12) ----------
  k_mega<<<NBLK,256>>>(wte,wpe,ln1_w,ln1_b,qkv_w,qkv_b,ao_w,ao_b,
                       ln2_w,ln2_b,fc_w,fc_b,pr_w,pr_b,lnf_w,lnf_b,lm_w,out);
}